// round 2
// baseline (speedup 1.0000x reference)
#include <cuda_runtime.h>
#include <math.h>

#define Bz 32
#define Tz 64
#define Sz 128
#define Hz 512
#define Vz 32000
#define Gz 2048   // 4*H
#define NLz 2

// ---------------- device scratch (no allocation allowed) ----------------
__device__ float d_x[Tz*Bz*Hz];        // embedded inputs [t][b][h]
__device__ float d_g0ih[Tz*Bz*Gz];     // precomputed layer0 ih gates (+both biases)
__device__ float d_gates[Bz*Gz];       // per-step gate buffer
__device__ float d_hstate[NLz*Bz*Hz];  // [l][b][h]
__device__ float d_cstate[NLz*Bz*Hz];
__device__ float d_cat1[Bz*2*Hz];      // [ inp1 | h1_prev ] per batch
__device__ float d_attq[Bz*Hz];        // attention query = h1 + inp1
__device__ float d_outs[Bz*Tz*Hz];     // ctx vectors [b][t][h]
__device__ float d_Wcat1[Gz*2*Hz];     // [ Wih1 | Whh1 ] concat along K
__device__ float d_bias0[Gz];
__device__ float d_bias1[Gz];

__device__ __forceinline__ float sigf(float x) { return 1.f / (1.f + expf(-x)); }

// ---------------- prep: bias sums, concat weights, state init ----------------
__global__ void prep_kernel(const float* __restrict__ Wih, const float* __restrict__ Whh,
                            const float* __restrict__ bih, const float* __restrict__ bhh,
                            const float* __restrict__ h0, const float* __restrict__ c0)
{
    int i = blockIdx.x * blockDim.x + threadIdx.x;
    if (i < Gz * 2 * Hz) {
        int n = i / (2*Hz), k = i % (2*Hz);
        d_Wcat1[i] = (k < Hz) ? Wih[(size_t)Gz*Hz + (size_t)n*Hz + k]
                              : Whh[(size_t)Gz*Hz + (size_t)n*Hz + (k - Hz)];
    }
    if (i < Gz) {
        d_bias0[i] = bih[i] + bhh[i];
        d_bias1[i] = bih[Gz + i] + bhh[Gz + i];
    }
    if (i < NLz*Bz*Hz) {
        d_hstate[i] = h0[i];
        d_cstate[i] = c0[i];
    }
    if (i < Bz*Hz) {
        // layer1 h_prev into second half of cat1
        int b = i / Hz, j = i % Hz;
        d_cat1[b*2*Hz + Hz + j] = h0[Bz*Hz + i];
    }
}

// ---------------- embedding (padding_idx = 0 -> zero row) ----------------
// ids buffer may be int32 or int64 depending on how the harness materialized
// jnp.int64 (JAX silently downcasts to int32 without x64). Probe: under an
// int64 little-endian layout, odd int32 words are the zero high-halves.
// Words 1,3,5 are in-bounds under BOTH layouts (element count 2048).
__global__ void embed_kernel(const int* __restrict__ ids32, const float* __restrict__ emb)
{
    int i = blockIdx.x * blockDim.x + threadIdx.x;
    if (i >= Tz*Bz*Hz) return;
    bool is64 = (ids32[1] == 0) && (ids32[3] == 0) && (ids32[5] == 0);
    int h = i % Hz;
    int tb = i / Hz;
    int b = tb % Bz;
    int t = tb / Bz;
    int idx = b*Tz + t;
    int id = is64 ? ids32[2*idx] : ids32[idx];
    if (id < 0 || id >= Vz) id = 0;     // defensive clamp (pad semantics)
    d_x[i] = (id == 0) ? 0.f : emb[(size_t)id*Hz + h];
}

// ---------------- generic tiled GEMM: C[M,N] = A[M,K] * B[N,K]^T (+bias[n]) (+Csrc[m,n]) -----
template<int BM, int BN, int BK, int TM, int TN>
__global__ __launch_bounds__((BM/TM)*(BN/TN))
void gemm_abt(const float* __restrict__ A, const float* __restrict__ Bm,
              const float* __restrict__ bias, const float* __restrict__ Csrc,
              float* __restrict__ C, int M, int N, int K)
{
    constexpr int NT = (BM/TM)*(BN/TN);
    __shared__ float As[BK][BM];
    __shared__ float Bs[BK][BN];

    const int m0 = blockIdx.y * BM;
    const int n0 = blockIdx.x * BN;
    const int tid = threadIdx.x;
    const int tx = tid % (BN/TN);
    const int ty = tid / (BN/TN);

    float acc[TM][TN];
#pragma unroll
    for (int i = 0; i < TM; ++i)
#pragma unroll
        for (int j = 0; j < TN; ++j) acc[i][j] = 0.f;

    for (int k0 = 0; k0 < K; k0 += BK) {
#pragma unroll
        for (int i = tid; i < BM*BK; i += NT) {
            int r = i / BK, kk = i % BK;
            As[kk][r] = A[(size_t)(m0 + r)*K + k0 + kk];
        }
#pragma unroll
        for (int i = tid; i < BN*BK; i += NT) {
            int r = i / BK, kk = i % BK;
            Bs[kk][r] = Bm[(size_t)(n0 + r)*K + k0 + kk];
        }
        __syncthreads();
#pragma unroll
        for (int kk = 0; kk < BK; ++kk) {
            float ra[TM], rb[TN];
#pragma unroll
            for (int i = 0; i < TM; ++i) ra[i] = As[kk][ty*TM + i];
#pragma unroll
            for (int j = 0; j < TN; ++j) rb[j] = Bs[kk][tx*TN + j];
#pragma unroll
            for (int i = 0; i < TM; ++i)
#pragma unroll
                for (int j = 0; j < TN; ++j) acc[i][j] += ra[i] * rb[j];
        }
        __syncthreads();
    }

#pragma unroll
    for (int i = 0; i < TM; ++i) {
        int m = m0 + ty*TM + i;
#pragma unroll
        for (int j = 0; j < TN; ++j) {
            int n = n0 + tx*TN + j;
            float v = acc[i][j];
            if (bias) v += bias[n];
            if (Csrc) v += Csrc[(size_t)m*N + n];
            C[(size_t)m*N + n] = v;
        }
    }
}

// ---------------- LSTM pointwise updates ----------------
__global__ void update0_kernel(int t)
{
    int i = blockIdx.x * blockDim.x + threadIdx.x;
    if (i >= Bz*Hz) return;
    int b = i / Hz, j = i % Hz;
    const float* gp = d_gates + (size_t)b*Gz;
    float ig = sigf(gp[j]);
    float fg = sigf(gp[Hz + j]);
    float gg = tanhf(gp[2*Hz + j]);
    float og = sigf(gp[3*Hz + j]);
    float c = fg * d_cstate[i] + ig * gg;
    float h = og * tanhf(c);
    d_cstate[i] = c;
    d_hstate[i] = h;
    // inp1 = h + x_t  (residual), goes into first half of cat1
    d_cat1[b*2*Hz + j] = h + d_x[((size_t)t*Bz + b)*Hz + j];
}

__global__ void update1_kernel()
{
    int i = blockIdx.x * blockDim.x + threadIdx.x;
    if (i >= Bz*Hz) return;
    int b = i / Hz, j = i % Hz;
    const float* gp = d_gates + (size_t)b*Gz;
    float ig = sigf(gp[j]);
    float fg = sigf(gp[Hz + j]);
    float gg = tanhf(gp[2*Hz + j]);
    float og = sigf(gp[3*Hz + j]);
    int si = Bz*Hz + i;  // layer1 state offset
    float c = fg * d_cstate[si] + ig * gg;
    float h = og * tanhf(c);
    d_cstate[si] = c;
    d_hstate[si] = h;
    float inp1 = d_cat1[b*2*Hz + j];
    d_attq[i] = h + inp1;               // attention query (residual)
    d_cat1[b*2*Hz + Hz + j] = h;        // h1 for next step's layer1 GEMM
}

// ---------------- attention: score -> log_softmax -> weighted sum (by LOG-softmax) -----
__global__ void attention_kernel(const float* __restrict__ ctx, int t)
{
    int b = blockIdx.x;
    int tid = threadIdx.x;
    __shared__ float sq[Hz];
    __shared__ float sc[Sz];
    __shared__ float s_lse;

    for (int i = tid; i < Hz; i += 256) sq[i] = d_attq[(size_t)b*Hz + i];
    __syncthreads();

    int warp = tid >> 5, lane = tid & 31;
    for (int s = warp; s < Sz; s += 8) {
        const float* cp = ctx + ((size_t)b*Sz + s)*Hz;
        float acc = 0.f;
        for (int h = lane; h < Hz; h += 32) acc += cp[h] * sq[h];
#pragma unroll
        for (int o = 16; o; o >>= 1) acc += __shfl_xor_sync(0xffffffffu, acc, o);
        if (lane == 0) sc[s] = acc;
    }
    __syncthreads();

    if (warp == 0) {
        float m = -1e30f;
        for (int s = lane; s < Sz; s += 32) m = fmaxf(m, sc[s]);
#pragma unroll
        for (int o = 16; o; o >>= 1) m = fmaxf(m, __shfl_xor_sync(0xffffffffu, m, o));
        float sum = 0.f;
        for (int s = lane; s < Sz; s += 32) sum += expf(sc[s] - m);
#pragma unroll
        for (int o = 16; o; o >>= 1) sum += __shfl_xor_sync(0xffffffffu, sum, o);
        if (lane == 0) s_lse = m + logf(sum);
    }
    __syncthreads();
    float lse = s_lse;

    float a0 = 0.f, a1 = 0.f;
    for (int s = 0; s < Sz; ++s) {
        float w = sc[s] - lse;   // LOG-softmax weight (faithful to reference)
        const float* cp = ctx + ((size_t)b*Sz + s)*Hz;
        a0 += cp[tid]       * w;
        a1 += cp[tid + 256] * w;
    }
    d_outs[((size_t)b*Tz + t)*Hz + tid]       = a0;
    d_outs[((size_t)b*Tz + t)*Hz + tid + 256] = a1;
}

// ---------------- tail: hT, cT after logits ----------------
__global__ void tail_kernel(float* __restrict__ out)
{
    int i = blockIdx.x * blockDim.x + threadIdx.x;
    const size_t base = (size_t)Bz*Tz*Vz;
    if (i < NLz*Bz*Hz)            out[base + i] = d_hstate[i];
    else if (i < 2*NLz*Bz*Hz)     out[base + i] = d_cstate[i - NLz*Bz*Hz];
}

// ---------------- launch ----------------
extern "C" void kernel_launch(void* const* d_in, const int* in_sizes, int n_in,
                              void* d_out, int out_size)
{
    const float* context = (const float*)d_in[0];
    const int*   dec     = (const int*)d_in[1];
    const float* h0      = (const float*)d_in[2];
    const float* c0      = (const float*)d_in[3];
    const float* emb     = (const float*)d_in[4];
    const float* Wih     = (const float*)d_in[5];
    const float* Whh     = (const float*)d_in[6];
    const float* bih     = (const float*)d_in[7];
    const float* bhh     = (const float*)d_in[8];
    const float* Wc      = (const float*)d_in[9];
    const float* bc      = (const float*)d_in[10];
    float* out = (float*)d_out;

    // device pointers to scratch symbols
    float *p_x, *p_g0ih, *p_gates, *p_h, *p_cat1, *p_outs, *p_Wcat1, *p_b0, *p_b1;
    cudaGetSymbolAddress((void**)&p_x,     d_x);
    cudaGetSymbolAddress((void**)&p_g0ih,  d_g0ih);
    cudaGetSymbolAddress((void**)&p_gates, d_gates);
    cudaGetSymbolAddress((void**)&p_h,     d_hstate);
    cudaGetSymbolAddress((void**)&p_cat1,  d_cat1);
    cudaGetSymbolAddress((void**)&p_outs,  d_outs);
    cudaGetSymbolAddress((void**)&p_Wcat1, d_Wcat1);
    cudaGetSymbolAddress((void**)&p_b0,    d_bias0);
    cudaGetSymbolAddress((void**)&p_b1,    d_bias1);

    // prep (covers largest range: G*2H = 2,097,152)
    prep_kernel<<<(Gz*2*Hz + 255)/256, 256>>>(Wih, Whh, bih, bhh, h0, c0);

    // embedding
    embed_kernel<<<(Tz*Bz*Hz + 255)/256, 256>>>(dec, emb);

    // precompute layer0 ih gates for ALL timesteps: [T*B, G] = x @ Wih0^T + (bih0+bhh0)
    {
        dim3 grid(Gz/64, (Tz*Bz)/64);
        gemm_abt<64,64,16,4,4><<<grid, 256>>>(p_x, Wih, p_b0, nullptr, p_g0ih, Tz*Bz, Gz, Hz);
    }

    // sequential scan
    for (int t = 0; t < Tz; ++t) {
        // layer0: gates = g0ih[t] + h0_prev @ Whh0^T
        gemm_abt<32,32,16,2,2><<<dim3(Gz/32, 1), 256>>>(
            p_h, Whh, nullptr, p_g0ih + (size_t)t*Bz*Gz, p_gates, Bz, Gz, Hz);
        update0_kernel<<<(Bz*Hz + 255)/256, 256>>>(t);

        // layer1: gates = [inp1|h1] @ [Wih1|Whh1]^T + (bih1+bhh1)
        gemm_abt<32,32,16,2,2><<<dim3(Gz/32, 1), 256>>>(
            p_cat1, p_Wcat1, p_b1, nullptr, p_gates, Bz, Gz, 2*Hz);
        update1_kernel<<<(Bz*Hz + 255)/256, 256>>>();

        attention_kernel<<<Bz, 256>>>(context, t);
    }

    // logits: [B*T, V] = outs @ Wc^T + bc   (outs is [b][t][h] row-major == m = b*T+t)
    {
        dim3 grid(Vz/64, (Bz*Tz)/64);
        gemm_abt<64,64,16,4,4><<<grid, 256>>>(p_outs, Wc, bc, nullptr, out, Bz*Tz, Vz, Hz);
    }

    // hT, cT
    if ((long long)out_size >= (long long)Bz*Tz*Vz + 2LL*NLz*Bz*Hz) {
        tail_kernel<<<(2*NLz*Bz*Hz + 255)/256, 256>>>(out);
    }
}

// round 3
// speedup vs baseline: 1.1306x; 1.1306x over previous
#include <cuda_runtime.h>
#include <math.h>

#define Bz 32
#define Tz 64
#define Sz 128
#define Hz 512
#define Vz 32000
#define Gz 2048   // 4*H
#define NBLK 128
#define NTHR 256

// ---------------- device scratch ----------------
__device__ __align__(16) float d_x[Tz*Bz*Hz];        // embedded inputs [t][b][h]
__device__ __align__(16) float d_g0ih[Tz*Bz*Gz];     // layer0 ih gates (+both biases)
__device__ __align__(16) float d_h0buf[2*Bz*Hz];     // ping-pong layer0 h
__device__ __align__(16) float d_h1buf[2*Bz*Hz];     // ping-pong layer1 h
__device__ __align__(16) float d_cstate[2*Bz*Hz];    // [l][b][h]
__device__ __align__(16) float d_cat1[Bz*Hz];        // inp1 = h0 + x (layer1 input, first K half)
__device__ __align__(16) float d_attq[Bz*Hz];        // attention query = h1 + inp1
__device__ __align__(16) float d_outs[Bz*Tz*Hz];     // ctx vectors [b][t][h]
__device__ __align__(16) float d_Wcat1[Gz*2*Hz];     // [ Wih1 | Whh1 ]
__device__ float d_bias0[Gz];
__device__ float d_bias1[Gz];
__device__ unsigned d_bar_cnt;

__device__ __forceinline__ float sigf(float x) { return 1.f / (1.f + expf(-x)); }

// ---------------- grid barrier (monotonic counter, reset per launch) -------
__device__ __forceinline__ void gbar(unsigned &nbar)
{
    nbar++;
    __syncthreads();
    if (threadIdx.x == 0) {
        __threadfence();                       // release (CCTL.IVALL on sm_103a)
        atomicAdd(&d_bar_cnt, 1u);
        unsigned target = nbar * (unsigned)NBLK;
        while (*(volatile unsigned*)&d_bar_cnt < target) __nanosleep(64);
        __threadfence();                       // acquire + L1 invalidate
    }
    __syncthreads();
}

__global__ void reset_kernel() { d_bar_cnt = 0u; }

// ---------------- prep ----------------
__global__ void prep_kernel(const float* __restrict__ Wih, const float* __restrict__ Whh,
                            const float* __restrict__ bih, const float* __restrict__ bhh,
                            const float* __restrict__ h0, const float* __restrict__ c0)
{
    int i = blockIdx.x * blockDim.x + threadIdx.x;
    if (i < Gz * 2 * Hz) {
        int n = i / (2*Hz), k = i % (2*Hz);
        d_Wcat1[i] = (k < Hz) ? Wih[(size_t)Gz*Hz + (size_t)n*Hz + k]
                              : Whh[(size_t)Gz*Hz + (size_t)n*Hz + (k - Hz)];
    }
    if (i < Gz) {
        d_bias0[i] = bih[i] + bhh[i];
        d_bias1[i] = bih[Gz + i] + bhh[Gz + i];
    }
    if (i < Bz*Hz) {
        d_h0buf[i] = h0[i];
        d_h1buf[i] = h0[Bz*Hz + i];
    }
    if (i < 2*Bz*Hz) d_cstate[i] = c0[i];
}

// ---------------- embedding (padding_idx = 0 -> zero row; int32/int64 probe) -----
__global__ void embed_kernel(const int* __restrict__ ids32, const float* __restrict__ emb)
{
    int i = blockIdx.x * blockDim.x + threadIdx.x;
    if (i >= Tz*Bz*Hz) return;
    bool is64 = (ids32[1] == 0) && (ids32[3] == 0) && (ids32[5] == 0);
    int h = i % Hz;
    int tb = i / Hz;
    int b = tb % Bz;
    int t = tb / Bz;
    int idx = b*Tz + t;
    int id = is64 ? ids32[2*idx] : ids32[idx];
    if (id < 0 || id >= Vz) id = 0;
    d_x[i] = (id == 0) ? 0.f : emb[(size_t)id*Hz + h];
}

// ---------------- generic tiled GEMM: C = A * B^T (+bias) ----------------
template<int BM, int BN, int BK, int TM, int TN>
__global__ __launch_bounds__((BM/TM)*(BN/TN))
void gemm_abt(const float* __restrict__ A, const float* __restrict__ Bm,
              const float* __restrict__ bias, float* __restrict__ C,
              int M, int N, int K)
{
    constexpr int NT = (BM/TM)*(BN/TN);
    __shared__ float As[BK][BM];
    __shared__ float Bs[BK][BN];

    const int m0 = blockIdx.y * BM;
    const int n0 = blockIdx.x * BN;
    const int tid = threadIdx.x;
    const int tx = tid % (BN/TN);
    const int ty = tid / (BN/TN);

    float acc[TM][TN];
#pragma unroll
    for (int i = 0; i < TM; ++i)
#pragma unroll
        for (int j = 0; j < TN; ++j) acc[i][j] = 0.f;

    for (int k0 = 0; k0 < K; k0 += BK) {
#pragma unroll
        for (int i = tid; i < BM*BK; i += NT) {
            int r = i / BK, kk = i % BK;
            As[kk][r] = A[(size_t)(m0 + r)*K + k0 + kk];
        }
#pragma unroll
        for (int i = tid; i < BN*BK; i += NT) {
            int r = i / BK, kk = i % BK;
            Bs[kk][r] = Bm[(size_t)(n0 + r)*K + k0 + kk];
        }
        __syncthreads();
#pragma unroll
        for (int kk = 0; kk < BK; ++kk) {
            float ra[TM], rb[TN];
#pragma unroll
            for (int i = 0; i < TM; ++i) ra[i] = As[kk][ty*TM + i];
#pragma unroll
            for (int j = 0; j < TN; ++j) rb[j] = Bs[kk][tx*TN + j];
#pragma unroll
            for (int i = 0; i < TM; ++i)
#pragma unroll
                for (int j = 0; j < TN; ++j) acc[i][j] += ra[i] * rb[j];
        }
        __syncthreads();
    }

#pragma unroll
    for (int i = 0; i < TM; ++i) {
        int m = m0 + ty*TM + i;
#pragma unroll
        for (int j = 0; j < TN; ++j) {
            int n = n0 + tx*TN + j;
            float v = acc[i][j];
            if (bias) v += bias[n];
            C[(size_t)m*N + n] = v;
        }
    }
}

// ---------------- persistent scan kernel: 64 steps, 3 grid barriers each ------
__global__ void __launch_bounds__(NTHR)
scan_kernel(const float* __restrict__ ctx, const float* __restrict__ Whh)
{
    __shared__ float sg[16][33];                 // gate partials [row][b]
    __shared__ __align__(16) float attq_s[Hz];
    __shared__ float sc_s[Sz];
    __shared__ float s_part[NTHR];
    __shared__ float s_lse;

    const int tid  = threadIdx.x;
    const int lane = tid & 31;
    const int w    = tid >> 5;
    const int blk  = blockIdx.x;
    const int j0   = blk * 4;                    // this block's 4 j's (layers)
    const int cb   = blk >> 2;                   // attention batch
    const int cq   = blk & 3;                    // attention H-quarter

    unsigned nbar = 0;

    // warp's two gate rows (lr = g*4 + jj)
    const int lr0 = 2*w, lr1 = 2*w + 1;
    const int n0 = (lr0 >> 2)*Hz + j0 + (lr0 & 3);
    const int n1 = (lr1 >> 2)*Hz + j0 + (lr1 & 3);

    for (int t = 0; t < Tz; ++t) {
        const int p = t & 1;
        const float* h0p = d_h0buf + p*Bz*Hz;
        float*       h0n = d_h0buf + (p^1)*Bz*Hz;
        const float* h1p = d_h1buf + p*Bz*Hz;
        float*       h1n = d_h1buf + (p^1)*Bz*Hz;

        // ================= Phase A: layer0 gates + LSTM update =================
        {
            const float4* W0 = (const float4*)(Whh + (size_t)n0*Hz);
            const float4* W1 = (const float4*)(Whh + (size_t)n1*Hz);
            float4 a0[4], a1[4];
#pragma unroll
            for (int i = 0; i < 4; ++i) { a0[i] = W0[lane + 32*i]; a1[i] = W1[lane + 32*i]; }
            const float4* Hp = (const float4*)h0p;    // [32][128]
            for (int b = 0; b < Bz; ++b) {
                float s0 = 0.f, s1 = 0.f;
#pragma unroll
                for (int i = 0; i < 4; ++i) {
                    float4 h4 = Hp[b*128 + lane + 32*i];
                    s0 += a0[i].x*h4.x + a0[i].y*h4.y + a0[i].z*h4.z + a0[i].w*h4.w;
                    s1 += a1[i].x*h4.x + a1[i].y*h4.y + a1[i].z*h4.z + a1[i].w*h4.w;
                }
#pragma unroll
                for (int o = 16; o; o >>= 1) {
                    s0 += __shfl_xor_sync(0xffffffffu, s0, o);
                    s1 += __shfl_xor_sync(0xffffffffu, s1, o);
                }
                if (lane == 0) { sg[lr0][b] = s0; sg[lr1][b] = s1; }
            }
            __syncthreads();
            if (tid < 128) {
                int b = tid >> 2, jj = tid & 3;
                int j = j0 + jj;
                const float* seed = d_g0ih + ((size_t)t*Bz + b)*Gz;   // includes biases
                float gi = sg[0  + jj][b] + seed[j];
                float gf = sg[4  + jj][b] + seed[Hz + j];
                float gg = sg[8  + jj][b] + seed[2*Hz + j];
                float go = sg[12 + jj][b] + seed[3*Hz + j];
                int ci = b*Hz + j;
                float c = sigf(gf)*d_cstate[ci] + sigf(gi)*tanhf(gg);
                float h = sigf(go)*tanhf(c);
                d_cstate[ci] = c;
                h0n[ci] = h;
                d_cat1[ci] = h + d_x[((size_t)t*Bz + b)*Hz + j];   // residual
            }
        }
        gbar(nbar);

        // ================= Phase B: layer1 gates (K=1024) + LSTM update =========
        {
            const float4* W0 = (const float4*)(d_Wcat1 + (size_t)n0*2*Hz);
            const float4* W1 = (const float4*)(d_Wcat1 + (size_t)n1*2*Hz);
            float4 a0[8], a1[8];
#pragma unroll
            for (int i = 0; i < 8; ++i) { a0[i] = W0[lane + 32*i]; a1[i] = W1[lane + 32*i]; }
            const float4* I4 = (const float4*)d_cat1;   // [32][128]
            const float4* H4 = (const float4*)h1p;      // [32][128]
            for (int b = 0; b < Bz; ++b) {
                float s0 = 0.f, s1 = 0.f;
#pragma unroll
                for (int i = 0; i < 4; ++i) {
                    float4 h4 = I4[b*128 + lane + 32*i];
                    s0 += a0[i].x*h4.x + a0[i].y*h4.y + a0[i].z*h4.z + a0[i].w*h4.w;
                    s1 += a1[i].x*h4.x + a1[i].y*h4.y + a1[i].z*h4.z + a1[i].w*h4.w;
                }
#pragma unroll
                for (int i = 0; i < 4; ++i) {
                    float4 h4 = H4[b*128 + lane + 32*i];
                    s0 += a0[4+i].x*h4.x + a0[4+i].y*h4.y + a0[4+i].z*h4.z + a0[4+i].w*h4.w;
                    s1 += a1[4+i].x*h4.x + a1[4+i].y*h4.y + a1[4+i].z*h4.z + a1[4+i].w*h4.w;
                }
#pragma unroll
                for (int o = 16; o; o >>= 1) {
                    s0 += __shfl_xor_sync(0xffffffffu, s0, o);
                    s1 += __shfl_xor_sync(0xffffffffu, s1, o);
                }
                if (lane == 0) { sg[lr0][b] = s0; sg[lr1][b] = s1; }
            }
            __syncthreads();
            if (tid < 128) {
                int b = tid >> 2, jj = tid & 3;
                int j = j0 + jj;
                float gi = sg[0  + jj][b] + d_bias1[j];
                float gf = sg[4  + jj][b] + d_bias1[Hz + j];
                float gg = sg[8  + jj][b] + d_bias1[2*Hz + j];
                float go = sg[12 + jj][b] + d_bias1[3*Hz + j];
                int ci = Bz*Hz + b*Hz + j;
                float c = sigf(gf)*d_cstate[ci] + sigf(gi)*tanhf(gg);
                float h = sigf(go)*tanhf(c);
                d_cstate[ci] = c;
                h1n[b*Hz + j] = h;
                d_attq[b*Hz + j] = h + d_cat1[b*Hz + j];   // residual -> attention query
            }
        }
        gbar(nbar);

        // ================= Phase C: attention (4 blocks per batch) =============
        {
            for (int i = tid; i < Hz; i += NTHR) attq_s[i] = d_attq[cb*Hz + i];
            __syncthreads();

            // all 128 scores (redundant across the 4 blocks of this batch)
            const float4* A4 = (const float4*)attq_s;
            for (int s = w*16; s < w*16 + 16; ++s) {
                const float4* C4 = (const float4*)(ctx + ((size_t)cb*Sz + s)*Hz);
                float acc = 0.f;
#pragma unroll
                for (int i = 0; i < 4; ++i) {
                    float4 c4 = C4[lane + 32*i];
                    float4 a4 = A4[lane + 32*i];
                    acc += c4.x*a4.x + c4.y*a4.y + c4.z*a4.z + c4.w*a4.w;
                }
#pragma unroll
                for (int o = 16; o; o >>= 1) acc += __shfl_xor_sync(0xffffffffu, acc, o);
                if (lane == 0) sc_s[s] = acc;
            }
            __syncthreads();

            if (w == 0) {
                float m = -1e30f;
                for (int s = lane; s < Sz; s += 32) m = fmaxf(m, sc_s[s]);
#pragma unroll
                for (int o = 16; o; o >>= 1) m = fmaxf(m, __shfl_xor_sync(0xffffffffu, m, o));
                float sm = 0.f;
                for (int s = lane; s < Sz; s += 32) sm += expf(sc_s[s] - m);
#pragma unroll
                for (int o = 16; o; o >>= 1) sm += __shfl_xor_sync(0xffffffffu, sm, o);
                if (lane == 0) s_lse = m + logf(sm);
            }
            __syncthreads();
            float lse = s_lse;

            // weighted sum by log-softmax over this block's H-quarter
            int h = cq*128 + (tid & 127);
            int sgrp = tid >> 7;  // 0 or 1
            float acc = 0.f;
            for (int s = sgrp*64; s < sgrp*64 + 64; ++s)
                acc += ctx[((size_t)cb*Sz + s)*Hz + h] * (sc_s[s] - lse);
            s_part[tid] = acc;
            __syncthreads();
            if (tid < 128)
                d_outs[((size_t)cb*Tz + t)*Hz + h] = s_part[tid] + s_part[tid + 128];
        }
        gbar(nbar);
    }
}

// ---------------- tail: hT, cT ----------------
__global__ void tail_kernel(float* __restrict__ out)
{
    int i = blockIdx.x * blockDim.x + threadIdx.x;
    const size_t base = (size_t)Bz*Tz*Vz;
    if (i < Bz*Hz)                 out[base + i] = d_h0buf[i];           // T even -> buf 0
    else if (i < 2*Bz*Hz)          out[base + i] = d_h1buf[i - Bz*Hz];
    else if (i < 4*Bz*Hz)          out[base + i] = d_cstate[i - 2*Bz*Hz];
}

// ---------------- launch ----------------
extern "C" void kernel_launch(void* const* d_in, const int* in_sizes, int n_in,
                              void* d_out, int out_size)
{
    const float* context = (const float*)d_in[0];
    const int*   dec     = (const int*)d_in[1];
    const float* h0      = (const float*)d_in[2];
    const float* c0      = (const float*)d_in[3];
    const float* emb     = (const float*)d_in[4];
    const float* Wih     = (const float*)d_in[5];
    const float* Whh     = (const float*)d_in[6];
    const float* bih     = (const float*)d_in[7];
    const float* bhh     = (const float*)d_in[8];
    const float* Wc      = (const float*)d_in[9];
    const float* bc      = (const float*)d_in[10];
    float* out = (float*)d_out;

    float *p_x, *p_g0ih, *p_outs, *p_b0;
    cudaGetSymbolAddress((void**)&p_x,    d_x);
    cudaGetSymbolAddress((void**)&p_g0ih, d_g0ih);
    cudaGetSymbolAddress((void**)&p_outs, d_outs);
    cudaGetSymbolAddress((void**)&p_b0,   d_bias0);

    reset_kernel<<<1, 1>>>();
    prep_kernel<<<(Gz*2*Hz + 255)/256, 256>>>(Wih, Whh, bih, bhh, h0, c0);
    embed_kernel<<<(Tz*Bz*Hz + 255)/256, 256>>>(dec, emb);

    // layer0 ih gates for ALL timesteps: [T*B, G] = x @ Wih0^T + (bih0+bhh0)
    {
        dim3 grid(Gz/64, (Tz*Bz)/64);
        gemm_abt<64,64,16,4,4><<<grid, 256>>>(p_x, Wih, p_b0, p_g0ih, Tz*Bz, Gz, Hz);
    }

    // persistent scan: all 64 steps, grid barriers inside
    scan_kernel<<<NBLK, NTHR>>>(context, Whh);

    // logits: [B*T, V] = outs @ Wc^T + bc
    {
        dim3 grid(Vz/64, (Bz*Tz)/64);
        gemm_abt<64,64,16,4,4><<<grid, 256>>>(p_outs, Wc, bc, out, Bz*Tz, Vz, Hz);
    }

    if ((long long)out_size >= (long long)Bz*Tz*Vz + 4LL*Bz*Hz) {
        tail_kernel<<<(4*Bz*Hz + 255)/256, 256>>>(out);
    }
}

// round 4
// speedup vs baseline: 2.3920x; 2.1156x over previous
#include <cuda_runtime.h>
#include <math.h>

#define Bz 32
#define Tz 64
#define Sz 128
#define Hz 512
#define Vz 32000
#define Gz 2048   // 4*H
#define NBLK 128
#define NTHR 256

// ---------------- device scratch ----------------
__device__ __align__(16) float d_x[Tz*Bz*Hz];        // embedded inputs [t][b][h]
__device__ __align__(16) float d_g0ih[Tz*Bz*Gz];     // layer0 ih gates (+both biases)
__device__ __align__(16) float d_h0buf[2*Bz*Hz];     // ping-pong layer0 h
__device__ __align__(16) float d_h1buf[2*Bz*Hz];     // ping-pong layer1 h
__device__ __align__(16) float d_cstate[2*Bz*Hz];    // [l][b][h]
__device__ __align__(16) float d_cat1[Bz*Hz];        // inp1 = h0 + x
__device__ __align__(16) float d_attq[Bz*Hz];        // attention query = h1 + inp1
__device__ __align__(16) float d_outs[Bz*Tz*Hz];     // ctx vectors [b][t][h]
__device__ __align__(16) float d_Wcat1[Gz*2*Hz];     // [ Wih1 | Whh1 ]
__device__ float d_bias0[Gz];
__device__ float d_bias1[Gz];
__device__ unsigned d_bar_cnt;

__device__ __forceinline__ float sigf(float x) { return 1.f / (1.f + expf(-x)); }

// ---------------- grid barrier ----------------
__device__ __forceinline__ void gbar(unsigned &nbar)
{
    nbar++;
    __syncthreads();
    if (threadIdx.x == 0) {
        __threadfence();
        atomicAdd(&d_bar_cnt, 1u);
        unsigned target = nbar * (unsigned)NBLK;
        while (*(volatile unsigned*)&d_bar_cnt < target) __nanosleep(32);
        __threadfence();
    }
    __syncthreads();
}

__global__ void reset_kernel() { d_bar_cnt = 0u; }

// ---------------- prep ----------------
__global__ void prep_kernel(const float* __restrict__ Wih, const float* __restrict__ Whh,
                            const float* __restrict__ bih, const float* __restrict__ bhh,
                            const float* __restrict__ h0, const float* __restrict__ c0)
{
    int i = blockIdx.x * blockDim.x + threadIdx.x;
    if (i < Gz * 2 * Hz) {
        int n = i / (2*Hz), k = i % (2*Hz);
        d_Wcat1[i] = (k < Hz) ? Wih[(size_t)Gz*Hz + (size_t)n*Hz + k]
                              : Whh[(size_t)Gz*Hz + (size_t)n*Hz + (k - Hz)];
    }
    if (i < Gz) {
        d_bias0[i] = bih[i] + bhh[i];
        d_bias1[i] = bih[Gz + i] + bhh[Gz + i];
    }
    if (i < Bz*Hz) {
        d_h0buf[i] = h0[i];
        d_h1buf[i] = h0[Bz*Hz + i];
    }
    if (i < 2*Bz*Hz) d_cstate[i] = c0[i];
}

// ---------------- embedding (padding_idx 0; int32/int64 probe) ----------------
__global__ void embed_kernel(const int* __restrict__ ids32, const float* __restrict__ emb)
{
    int i = blockIdx.x * blockDim.x + threadIdx.x;
    if (i >= Tz*Bz*Hz) return;
    bool is64 = (ids32[1] == 0) && (ids32[3] == 0) && (ids32[5] == 0);
    int h = i % Hz;
    int tb = i / Hz;
    int b = tb % Bz;
    int t = tb / Bz;
    int idx = b*Tz + t;
    int id = is64 ? ids32[2*idx] : ids32[idx];
    if (id < 0 || id >= Vz) id = 0;
    d_x[i] = (id == 0) ? 0.f : emb[(size_t)id*Hz + h];
}

// ---------------- GEMM: C[M,N] = A[M,K] * B[N,K]^T (+bias) ----------------
// BM=128, BN=64, BK=16, TM=8, TN=4, 256 threads, float4 smem reads.
template<int BM, int BN, int BK, int TM, int TN>
__global__ __launch_bounds__((BM/TM)*(BN/TN))
void gemm_abt(const float* __restrict__ A, const float* __restrict__ Bm,
              const float* __restrict__ bias, float* __restrict__ C,
              int M, int N, int K)
{
    __shared__ float As[BK][BM];
    __shared__ float Bs[BK][BN];

    const int m0 = blockIdx.y * BM;
    const int n0 = blockIdx.x * BN;
    const int tid = threadIdx.x;
    const int tx = tid % (BN/TN);   // 16
    const int ty = tid / (BN/TN);   // 16

    float acc[TM][TN];
#pragma unroll
    for (int i = 0; i < TM; ++i)
#pragma unroll
        for (int j = 0; j < TN; ++j) acc[i][j] = 0.f;

    // A-load mapping: 512 float4 per tile, 2 per thread, coalesced along k
    const int ar0 = tid >> 2;            // rows tid/4 and tid/4+64
    const int ak0 = (tid & 3) * 4;       // k offset within BK
    // B-load mapping: 256 float4 per tile, 1 per thread
    const int br  = tid >> 2;
    const int bk0 = (tid & 3) * 4;

    for (int k0 = 0; k0 < K; k0 += BK) {
        {
            float4 v0 = *(const float4*)&A[(size_t)(m0 + ar0)*K + k0 + ak0];
            float4 v1 = *(const float4*)&A[(size_t)(m0 + ar0 + 64)*K + k0 + ak0];
            As[ak0+0][ar0] = v0.x; As[ak0+1][ar0] = v0.y;
            As[ak0+2][ar0] = v0.z; As[ak0+3][ar0] = v0.w;
            As[ak0+0][ar0+64] = v1.x; As[ak0+1][ar0+64] = v1.y;
            As[ak0+2][ar0+64] = v1.z; As[ak0+3][ar0+64] = v1.w;
        }
        {
            float4 v = *(const float4*)&Bm[(size_t)(n0 + br)*K + k0 + bk0];
            Bs[bk0+0][br] = v.x; Bs[bk0+1][br] = v.y;
            Bs[bk0+2][br] = v.z; Bs[bk0+3][br] = v.w;
        }
        __syncthreads();
#pragma unroll
        for (int kk = 0; kk < BK; ++kk) {
            float a[TM], b[TN];
            *(float4*)&a[0] = *(const float4*)&As[kk][ty*TM];
            *(float4*)&a[4] = *(const float4*)&As[kk][ty*TM + 4];
            *(float4*)&b[0] = *(const float4*)&Bs[kk][tx*TN];
#pragma unroll
            for (int i = 0; i < TM; ++i)
#pragma unroll
                for (int j = 0; j < TN; ++j) acc[i][j] += a[i] * b[j];
        }
        __syncthreads();
    }

#pragma unroll
    for (int i = 0; i < TM; ++i) {
        int m = m0 + ty*TM + i;
        int n = n0 + tx*TN;
        float4 v;
        v.x = acc[i][0]; v.y = acc[i][1]; v.z = acc[i][2]; v.w = acc[i][3];
        if (bias) {
            v.x += bias[n]; v.y += bias[n+1]; v.z += bias[n+2]; v.w += bias[n+3];
        }
        *(float4*)&C[(size_t)m*N + n] = v;
    }
}

// ---------------- persistent scan: smem-staged h, reg-resident weights -------
__global__ void __launch_bounds__(NTHR, 1)
scan_kernel(const float* __restrict__ ctx, const float* __restrict__ Whh)
{
    __shared__ __align__(16) float hbuf[8192];   // 32KB: 16 batches x 512
    __shared__ float sg[16][33];                 // gate partials [row][b]
    __shared__ __align__(16) float attq_s[Hz];
    __shared__ float sc_s[Sz];
    __shared__ float s_part[NTHR];
    __shared__ float s_lse;

    const int tid  = threadIdx.x;
    const int lane = tid & 31;
    const int w    = tid >> 5;
    const int blk  = blockIdx.x;
    const int j0   = blk * 4;
    const int cb   = blk >> 2;
    const int cq   = blk & 3;

    const int lr0 = 2*w, lr1 = 2*w + 1;
    const int n0 = (lr0 >> 2)*Hz + j0 + (lr0 & 3);
    const int n1 = (lr1 >> 2)*Hz + j0 + (lr1 & 3);

    // ---- hoist weight rows into registers (loop-invariant across t) ----
    float4 aA0[4], aA1[4], aB0[8], aB1[8];
    {
        const float4* W0 = (const float4*)(Whh + (size_t)n0*Hz);
        const float4* W1 = (const float4*)(Whh + (size_t)n1*Hz);
#pragma unroll
        for (int i = 0; i < 4; ++i) { aA0[i] = W0[lane + 32*i]; aA1[i] = W1[lane + 32*i]; }
        const float4* C0 = (const float4*)(d_Wcat1 + (size_t)n0*2*Hz);
        const float4* C1 = (const float4*)(d_Wcat1 + (size_t)n1*2*Hz);
#pragma unroll
        for (int i = 0; i < 8; ++i) { aB0[i] = C0[lane + 32*i]; aB1[i] = C1[lane + 32*i]; }
    }

    unsigned nbar = 0;
    float4* hb4 = (float4*)hbuf;

    for (int t = 0; t < Tz; ++t) {
        const int p = t & 1;
        const float* h0p = d_h0buf + p*Bz*Hz;
        float*       h0n = d_h0buf + (p^1)*Bz*Hz;
        const float* h1p = d_h1buf + p*Bz*Hz;
        float*       h1n = d_h1buf + (p^1)*Bz*Hz;

        // ================= Phase A: layer0 gates =================
        {
            const float4* Hp = (const float4*)h0p;   // [32][128]
            for (int chunk = 0; chunk < 2; ++chunk) {
#pragma unroll
                for (int idx = tid; idx < 2048; idx += NTHR)
                    hb4[idx] = Hp[chunk*2048 + idx];
                __syncthreads();
#pragma unroll 2
                for (int bl = 0; bl < 16; ++bl) {
                    float s0 = 0.f, s1 = 0.f;
                    const float4* hr = hb4 + bl*128;
#pragma unroll
                    for (int i = 0; i < 4; ++i) {
                        float4 h4 = hr[lane + 32*i];
                        s0 += aA0[i].x*h4.x + aA0[i].y*h4.y + aA0[i].z*h4.z + aA0[i].w*h4.w;
                        s1 += aA1[i].x*h4.x + aA1[i].y*h4.y + aA1[i].z*h4.z + aA1[i].w*h4.w;
                    }
#pragma unroll
                    for (int o = 16; o; o >>= 1) {
                        s0 += __shfl_xor_sync(0xffffffffu, s0, o);
                        s1 += __shfl_xor_sync(0xffffffffu, s1, o);
                    }
                    if (lane == 0) { sg[lr0][chunk*16 + bl] = s0; sg[lr1][chunk*16 + bl] = s1; }
                }
                __syncthreads();
            }
            if (tid < 128) {
                int b = tid >> 2, jj = tid & 3;
                int j = j0 + jj;
                const float* seed = d_g0ih + ((size_t)t*Bz + b)*Gz;
                float gi = sg[0  + jj][b] + seed[j];
                float gf = sg[4  + jj][b] + seed[Hz + j];
                float gg = sg[8  + jj][b] + seed[2*Hz + j];
                float go = sg[12 + jj][b] + seed[3*Hz + j];
                int ci = b*Hz + j;
                float c = sigf(gf)*d_cstate[ci] + sigf(gi)*tanhf(gg);
                float h = sigf(go)*tanhf(c);
                d_cstate[ci] = c;
                h0n[ci] = h;
                d_cat1[ci] = h + d_x[((size_t)t*Bz + b)*Hz + j];
            }
        }
        gbar(nbar);

        // ================= Phase B: layer1 gates (K=1024 in 2 halves) ==========
        {
            for (int half = 0; half < 2; ++half) {
                const float4* src = half ? (const float4*)h1p : (const float4*)d_cat1;
                const float4* wr0 = half ? (aB0 + 4) : aB0;
                const float4* wr1 = half ? (aB1 + 4) : aB1;
                for (int chunk = 0; chunk < 2; ++chunk) {
#pragma unroll
                    for (int idx = tid; idx < 2048; idx += NTHR)
                        hb4[idx] = src[chunk*2048 + idx];
                    __syncthreads();
#pragma unroll 2
                    for (int bl = 0; bl < 16; ++bl) {
                        float s0 = 0.f, s1 = 0.f;
                        const float4* hr = hb4 + bl*128;
#pragma unroll
                        for (int i = 0; i < 4; ++i) {
                            float4 h4 = hr[lane + 32*i];
                            s0 += wr0[i].x*h4.x + wr0[i].y*h4.y + wr0[i].z*h4.z + wr0[i].w*h4.w;
                            s1 += wr1[i].x*h4.x + wr1[i].y*h4.y + wr1[i].z*h4.z + wr1[i].w*h4.w;
                        }
#pragma unroll
                        for (int o = 16; o; o >>= 1) {
                            s0 += __shfl_xor_sync(0xffffffffu, s0, o);
                            s1 += __shfl_xor_sync(0xffffffffu, s1, o);
                        }
                        if (lane == 0) {
                            int b = chunk*16 + bl;
                            if (half == 0) { sg[lr0][b] = s0; sg[lr1][b] = s1; }
                            else           { sg[lr0][b] += s0; sg[lr1][b] += s1; }
                        }
                    }
                    __syncthreads();
                }
            }
            if (tid < 128) {
                int b = tid >> 2, jj = tid & 3;
                int j = j0 + jj;
                float gi = sg[0  + jj][b] + d_bias1[j];
                float gf = sg[4  + jj][b] + d_bias1[Hz + j];
                float gg = sg[8  + jj][b] + d_bias1[2*Hz + j];
                float go = sg[12 + jj][b] + d_bias1[3*Hz + j];
                int ci = Bz*Hz + b*Hz + j;
                float c = sigf(gf)*d_cstate[ci] + sigf(gi)*tanhf(gg);
                float h = sigf(go)*tanhf(c);
                d_cstate[ci] = c;
                h1n[b*Hz + j] = h;
                d_attq[b*Hz + j] = h + d_cat1[b*Hz + j];
            }
        }
        gbar(nbar);

        // ================= Phase C: attention =================
        {
            for (int i = tid; i < Hz; i += NTHR) attq_s[i] = d_attq[cb*Hz + i];
            __syncthreads();

            const float4* A4 = (const float4*)attq_s;
            for (int s = w*16; s < w*16 + 16; ++s) {
                const float4* C4 = (const float4*)(ctx + ((size_t)cb*Sz + s)*Hz);
                float acc = 0.f;
#pragma unroll
                for (int i = 0; i < 4; ++i) {
                    float4 c4 = C4[lane + 32*i];
                    float4 a4 = A4[lane + 32*i];
                    acc += c4.x*a4.x + c4.y*a4.y + c4.z*a4.z + c4.w*a4.w;
                }
#pragma unroll
                for (int o = 16; o; o >>= 1) acc += __shfl_xor_sync(0xffffffffu, acc, o);
                if (lane == 0) sc_s[s] = acc;
            }
            __syncthreads();

            if (w == 0) {
                float m = -1e30f;
                for (int s = lane; s < Sz; s += 32) m = fmaxf(m, sc_s[s]);
#pragma unroll
                for (int o = 16; o; o >>= 1) m = fmaxf(m, __shfl_xor_sync(0xffffffffu, m, o));
                float sm = 0.f;
                for (int s = lane; s < Sz; s += 32) sm += expf(sc_s[s] - m);
#pragma unroll
                for (int o = 16; o; o >>= 1) sm += __shfl_xor_sync(0xffffffffu, sm, o);
                if (lane == 0) s_lse = m + logf(sm);
            }
            __syncthreads();
            float lse = s_lse;

            int h = cq*128 + (tid & 127);
            int sgrp = tid >> 7;
            float acc = 0.f;
            for (int s = sgrp*64; s < sgrp*64 + 64; ++s)
                acc += ctx[((size_t)cb*Sz + s)*Hz + h] * (sc_s[s] - lse);
            s_part[tid] = acc;
            __syncthreads();
            if (tid < 128)
                d_outs[((size_t)cb*Tz + t)*Hz + h] = s_part[tid] + s_part[tid + 128];
        }
        gbar(nbar);
    }
}

// ---------------- tail: hT, cT ----------------
__global__ void tail_kernel(float* __restrict__ out)
{
    int i = blockIdx.x * blockDim.x + threadIdx.x;
    const size_t base = (size_t)Bz*Tz*Vz;
    if (i < Bz*Hz)                 out[base + i] = d_h0buf[i];       // T even -> buf 0
    else if (i < 2*Bz*Hz)          out[base + i] = d_h1buf[i - Bz*Hz];
    else if (i < 4*Bz*Hz)          out[base + i] = d_cstate[i - 2*Bz*Hz];
}

// ---------------- launch ----------------
extern "C" void kernel_launch(void* const* d_in, const int* in_sizes, int n_in,
                              void* d_out, int out_size)
{
    const float* context = (const float*)d_in[0];
    const int*   dec     = (const int*)d_in[1];
    const float* h0      = (const float*)d_in[2];
    const float* c0      = (const float*)d_in[3];
    const float* emb     = (const float*)d_in[4];
    const float* Wih     = (const float*)d_in[5];
    const float* Whh     = (const float*)d_in[6];
    const float* bih     = (const float*)d_in[7];
    const float* bhh     = (const float*)d_in[8];
    const float* Wc      = (const float*)d_in[9];
    const float* bc      = (const float*)d_in[10];
    float* out = (float*)d_out;

    float *p_x, *p_g0ih, *p_outs, *p_b0;
    cudaGetSymbolAddress((void**)&p_x,    d_x);
    cudaGetSymbolAddress((void**)&p_g0ih, d_g0ih);
    cudaGetSymbolAddress((void**)&p_outs, d_outs);
    cudaGetSymbolAddress((void**)&p_b0,   d_bias0);

    reset_kernel<<<1, 1>>>();
    prep_kernel<<<(Gz*2*Hz + 255)/256, 256>>>(Wih, Whh, bih, bhh, h0, c0);
    embed_kernel<<<(Tz*Bz*Hz + 255)/256, 256>>>(dec, emb);

    // layer0 ih gates for ALL timesteps: [T*B, G] = x @ Wih0^T + (bih0+bhh0)
    {
        dim3 grid(Gz/64, (Tz*Bz)/128);
        gemm_abt<128,64,16,8,4><<<grid, 256>>>(p_x, Wih, p_b0, p_g0ih, Tz*Bz, Gz, Hz);
    }

    // persistent scan
    scan_kernel<<<NBLK, NTHR>>>(context, Whh);

    // logits: [B*T, V] = outs @ Wc^T + bc
    {
        dim3 grid(Vz/64, (Bz*Tz)/128);
        gemm_abt<128,64,16,8,4><<<grid, 256>>>(p_outs, Wc, bc, out, Bz*Tz, Vz, Hz);
    }

    if ((long long)out_size >= (long long)Bz*Tz*Vz + 4LL*Bz*Hz) {
        tail_kernel<<<(4*Bz*Hz + 255)/256, 256>>>(out);
    }
}

// round 5
// speedup vs baseline: 2.5665x; 1.0730x over previous
#include <cuda_runtime.h>
#include <math.h>

#define Bz 32
#define Tz 64
#define Sz 128
#define Hz 512
#define Vz 32000
#define Gz 2048   // 4*H
#define NBLK 128
#define NTHR 256

// ---------------- device scratch ----------------
__device__ __align__(16) float d_x[Tz*Bz*Hz];        // embedded inputs [t][b][h]
__device__ __align__(16) float d_g0ih[Tz*Bz*Gz];     // layer0 ih gates (+both biases)
__device__ __align__(16) float d_h0buf[2*Bz*Hz];     // ping-pong layer0 h
__device__ __align__(16) float d_h1buf[2*Bz*Hz];     // ping-pong layer1 h
__device__ __align__(16) float d_cstate[2*Bz*Hz];    // [l][b][h]
__device__ __align__(16) float d_cat1[Bz*Hz];        // inp1 = h0 + x
__device__ __align__(16) float d_attq[Bz*Hz];        // attention query = h1 + inp1
__device__ __align__(16) float d_outs[Bz*Tz*Hz];     // ctx vectors [b][t][h]
__device__ __align__(16) float d_Wcat1[Gz*2*Hz];     // [ Wih1 | Whh1 ]
__device__ float d_bias0[Gz];
__device__ float d_bias1[Gz];
__device__ unsigned d_bar_cnt;

__device__ __forceinline__ float sigf(float x) { return 1.f / (1.f + expf(-x)); }

// ---------------- packed f32x2 helpers (sm_103a) ----------------
__device__ __forceinline__ void ffma2(unsigned long long &d,
                                      unsigned long long a,
                                      unsigned long long b)
{
    asm("fma.rn.f32x2 %0, %1, %2, %0;" : "+l"(d) : "l"(a), "l"(b));
}
__device__ __forceinline__ unsigned long long dup2(float x)
{
    unsigned long long r;
    asm("mov.b64 %0, {%1, %1};" : "=l"(r) : "r"(__float_as_uint(x)));
    return r;
}
__device__ __forceinline__ float2 unpack2(unsigned long long v)
{
    unsigned lo, hi;
    asm("mov.b64 {%0, %1}, %2;" : "=r"(lo), "=r"(hi) : "l"(v));
    return make_float2(__uint_as_float(lo), __uint_as_float(hi));
}

// ---------------- grid barrier ----------------
__device__ __forceinline__ void gbar(unsigned &nbar)
{
    nbar++;
    __syncthreads();
    if (threadIdx.x == 0) {
        __threadfence();
        atomicAdd(&d_bar_cnt, 1u);
        unsigned target = nbar * (unsigned)NBLK;
        while (*(volatile unsigned*)&d_bar_cnt < target) __nanosleep(32);
        __threadfence();
    }
    __syncthreads();
}

__global__ void reset_kernel() { d_bar_cnt = 0u; }

// ---------------- prep ----------------
__global__ void prep_kernel(const float* __restrict__ Wih, const float* __restrict__ Whh,
                            const float* __restrict__ bih, const float* __restrict__ bhh,
                            const float* __restrict__ h0, const float* __restrict__ c0)
{
    int i = blockIdx.x * blockDim.x + threadIdx.x;
    if (i < Gz * 2 * Hz) {
        int n = i / (2*Hz), k = i % (2*Hz);
        d_Wcat1[i] = (k < Hz) ? Wih[(size_t)Gz*Hz + (size_t)n*Hz + k]
                              : Whh[(size_t)Gz*Hz + (size_t)n*Hz + (k - Hz)];
    }
    if (i < Gz) {
        d_bias0[i] = bih[i] + bhh[i];
        d_bias1[i] = bih[Gz + i] + bhh[Gz + i];
    }
    if (i < Bz*Hz) {
        d_h0buf[i] = h0[i];
        d_h1buf[i] = h0[Bz*Hz + i];
    }
    if (i < 2*Bz*Hz) d_cstate[i] = c0[i];
}

// ---------------- embedding (padding_idx 0; int32/int64 probe) ----------------
__global__ void embed_kernel(const int* __restrict__ ids32, const float* __restrict__ emb)
{
    int i = blockIdx.x * blockDim.x + threadIdx.x;
    if (i >= Tz*Bz*Hz) return;
    bool is64 = (ids32[1] == 0) && (ids32[3] == 0) && (ids32[5] == 0);
    int h = i % Hz;
    int tb = i / Hz;
    int b = tb % Bz;
    int t = tb / Bz;
    int idx = b*Tz + t;
    int id = is64 ? ids32[2*idx] : ids32[idx];
    if (id < 0 || id >= Vz) id = 0;
    d_x[i] = (id == 0) ? 0.f : emb[(size_t)id*Hz + h];
}

// ---------------- GEMM: C[M,N] = A[M,K] * B[N,K]^T (+bias), FFMA2 inner loop ----
// BM=128, BN=64, BK=16, TM=8, TN=4, 256 threads.
template<int BM, int BN, int BK, int TM, int TN>
__global__ __launch_bounds__((BM/TM)*(BN/TN))
void gemm_abt(const float* __restrict__ A, const float* __restrict__ Bm,
              const float* __restrict__ bias, float* __restrict__ C,
              int M, int N, int K)
{
    __shared__ __align__(16) float As[BK][BM];
    __shared__ __align__(16) float Bs[BK][BN];

    const int m0 = blockIdx.y * BM;
    const int n0 = blockIdx.x * BN;
    const int tid = threadIdx.x;
    const int tx = tid % (BN/TN);   // 16
    const int ty = tid / (BN/TN);   // 16

    // packed accumulators: acc2[i2][j] = (row 2*i2, col j ; row 2*i2+1, col j)
    unsigned long long acc2[TM/2][TN];
#pragma unroll
    for (int i = 0; i < TM/2; ++i)
#pragma unroll
        for (int j = 0; j < TN; ++j) acc2[i][j] = 0ull;

    const int ar0 = tid >> 2;            // A rows tid/4 and tid/4+64
    const int ak0 = (tid & 3) * 4;
    const int br  = tid >> 2;
    const int bk0 = (tid & 3) * 4;

    for (int k0 = 0; k0 < K; k0 += BK) {
        {
            float4 v0 = *(const float4*)&A[(size_t)(m0 + ar0)*K + k0 + ak0];
            float4 v1 = *(const float4*)&A[(size_t)(m0 + ar0 + 64)*K + k0 + ak0];
            As[ak0+0][ar0] = v0.x; As[ak0+1][ar0] = v0.y;
            As[ak0+2][ar0] = v0.z; As[ak0+3][ar0] = v0.w;
            As[ak0+0][ar0+64] = v1.x; As[ak0+1][ar0+64] = v1.y;
            As[ak0+2][ar0+64] = v1.z; As[ak0+3][ar0+64] = v1.w;
        }
        {
            float4 v = *(const float4*)&Bm[(size_t)(n0 + br)*K + k0 + bk0];
            Bs[bk0+0][br] = v.x; Bs[bk0+1][br] = v.y;
            Bs[bk0+2][br] = v.z; Bs[bk0+3][br] = v.w;
        }
        __syncthreads();
#pragma unroll
        for (int kk = 0; kk < BK; ++kk) {
            // adjacent rows of As are contiguous -> direct f32x2 pairs
            ulonglong2 pa = *(const ulonglong2*)&As[kk][ty*TM];
            ulonglong2 pb = *(const ulonglong2*)&As[kk][ty*TM + 4];
            unsigned long long ap0 = pa.x, ap1 = pa.y, ap2 = pb.x, ap3 = pb.y;
            float4 bq = *(const float4*)&Bs[kk][tx*TN];
            unsigned long long bd0 = dup2(bq.x), bd1 = dup2(bq.y);
            unsigned long long bd2 = dup2(bq.z), bd3 = dup2(bq.w);
            ffma2(acc2[0][0], ap0, bd0); ffma2(acc2[0][1], ap0, bd1);
            ffma2(acc2[0][2], ap0, bd2); ffma2(acc2[0][3], ap0, bd3);
            ffma2(acc2[1][0], ap1, bd0); ffma2(acc2[1][1], ap1, bd1);
            ffma2(acc2[1][2], ap1, bd2); ffma2(acc2[1][3], ap1, bd3);
            ffma2(acc2[2][0], ap2, bd0); ffma2(acc2[2][1], ap2, bd1);
            ffma2(acc2[2][2], ap2, bd2); ffma2(acc2[2][3], ap2, bd3);
            ffma2(acc2[3][0], ap3, bd0); ffma2(acc2[3][1], ap3, bd1);
            ffma2(acc2[3][2], ap3, bd2); ffma2(acc2[3][3], ap3, bd3);
        }
        __syncthreads();
    }

    const int n = n0 + tx*TN;
    float4 bv = make_float4(0.f, 0.f, 0.f, 0.f);
    if (bias) { bv.x = bias[n]; bv.y = bias[n+1]; bv.z = bias[n+2]; bv.w = bias[n+3]; }
#pragma unroll
    for (int i2 = 0; i2 < TM/2; ++i2) {
        float2 c0 = unpack2(acc2[i2][0]);
        float2 c1 = unpack2(acc2[i2][1]);
        float2 c2 = unpack2(acc2[i2][2]);
        float2 c3 = unpack2(acc2[i2][3]);
        int m = m0 + ty*TM + 2*i2;
        float4 v0 = make_float4(c0.x + bv.x, c1.x + bv.y, c2.x + bv.z, c3.x + bv.w);
        float4 v1 = make_float4(c0.y + bv.x, c1.y + bv.y, c2.y + bv.z, c3.y + bv.w);
        *(float4*)&C[(size_t)m*N + n]       = v0;
        *(float4*)&C[(size_t)(m+1)*N + n]   = v1;
    }
}

// ---------------- persistent scan: smem-staged h, reg weights, 2 barriers/step ----
__global__ void __launch_bounds__(NTHR, 1)
scan_kernel(const float* __restrict__ ctx, const float* __restrict__ Whh)
{
    __shared__ __align__(16) float hbuf[8192];   // 32KB: 16 batches x 512
    __shared__ float sg[16][33];                 // gate partials [row][b]
    __shared__ __align__(16) float attq_s[Hz];
    __shared__ float sc_s[Sz];
    __shared__ float s_part[NTHR];
    __shared__ float s_lse;

    const int tid  = threadIdx.x;
    const int lane = tid & 31;
    const int w    = tid >> 5;
    const int blk  = blockIdx.x;
    const int j0   = blk * 4;
    const int cb   = blk >> 2;
    const int cq   = blk & 3;

    const int lr0 = 2*w, lr1 = 2*w + 1;
    const int n0 = (lr0 >> 2)*Hz + j0 + (lr0 & 3);
    const int n1 = (lr1 >> 2)*Hz + j0 + (lr1 & 3);

    // hoist weight rows into registers (loop-invariant)
    float4 aA0[4], aA1[4], aB0[8], aB1[8];
    {
        const float4* W0 = (const float4*)(Whh + (size_t)n0*Hz);
        const float4* W1 = (const float4*)(Whh + (size_t)n1*Hz);
#pragma unroll
        for (int i = 0; i < 4; ++i) { aA0[i] = W0[lane + 32*i]; aA1[i] = W1[lane + 32*i]; }
        const float4* C0 = (const float4*)(d_Wcat1 + (size_t)n0*2*Hz);
        const float4* C1 = (const float4*)(d_Wcat1 + (size_t)n1*2*Hz);
#pragma unroll
        for (int i = 0; i < 8; ++i) { aB0[i] = C0[lane + 32*i]; aB1[i] = C1[lane + 32*i]; }
    }

    unsigned nbar = 0;
    float4* hb4 = (float4*)hbuf;

    for (int t = 0; t < Tz; ++t) {
        const int p = t & 1;
        const float* h0p = d_h0buf + p*Bz*Hz;
        float*       h0n = d_h0buf + (p^1)*Bz*Hz;
        const float* h1p = d_h1buf + p*Bz*Hz;
        float*       h1n = d_h1buf + (p^1)*Bz*Hz;

        // ================= Phase A: layer0 gates =================
        {
            const float4* Hp = (const float4*)h0p;
            for (int chunk = 0; chunk < 2; ++chunk) {
#pragma unroll
                for (int idx = tid; idx < 2048; idx += NTHR)
                    hb4[idx] = Hp[chunk*2048 + idx];
                __syncthreads();
#pragma unroll 2
                for (int bl = 0; bl < 16; ++bl) {
                    float s0 = 0.f, s1 = 0.f;
                    const float4* hr = hb4 + bl*128;
#pragma unroll
                    for (int i = 0; i < 4; ++i) {
                        float4 h4 = hr[lane + 32*i];
                        s0 += aA0[i].x*h4.x + aA0[i].y*h4.y + aA0[i].z*h4.z + aA0[i].w*h4.w;
                        s1 += aA1[i].x*h4.x + aA1[i].y*h4.y + aA1[i].z*h4.z + aA1[i].w*h4.w;
                    }
#pragma unroll
                    for (int o = 16; o; o >>= 1) {
                        s0 += __shfl_xor_sync(0xffffffffu, s0, o);
                        s1 += __shfl_xor_sync(0xffffffffu, s1, o);
                    }
                    if (lane == 0) { sg[lr0][chunk*16 + bl] = s0; sg[lr1][chunk*16 + bl] = s1; }
                }
                __syncthreads();
            }
            if (tid < 128) {
                int b = tid >> 2, jj = tid & 3;
                int j = j0 + jj;
                const float* seed = d_g0ih + ((size_t)t*Bz + b)*Gz;
                float gi = sg[0  + jj][b] + seed[j];
                float gf = sg[4  + jj][b] + seed[Hz + j];
                float gg = sg[8  + jj][b] + seed[2*Hz + j];
                float go = sg[12 + jj][b] + seed[3*Hz + j];
                int ci = b*Hz + j;
                float c = sigf(gf)*d_cstate[ci] + sigf(gi)*tanhf(gg);
                float h = sigf(go)*tanhf(c);
                d_cstate[ci] = c;
                h0n[ci] = h;
                d_cat1[ci] = h + d_x[((size_t)t*Bz + b)*Hz + j];
            }
        }
        gbar(nbar);

        // ================= Phase B: layer1 gates (K=1024) =================
        {
            for (int half = 0; half < 2; ++half) {
                const float4* src = half ? (const float4*)h1p : (const float4*)d_cat1;
                const float4* wr0 = half ? (aB0 + 4) : aB0;
                const float4* wr1 = half ? (aB1 + 4) : aB1;
                for (int chunk = 0; chunk < 2; ++chunk) {
#pragma unroll
                    for (int idx = tid; idx < 2048; idx += NTHR)
                        hb4[idx] = src[chunk*2048 + idx];
                    __syncthreads();
#pragma unroll 2
                    for (int bl = 0; bl < 16; ++bl) {
                        float s0 = 0.f, s1 = 0.f;
                        const float4* hr = hb4 + bl*128;
#pragma unroll
                        for (int i = 0; i < 4; ++i) {
                            float4 h4 = hr[lane + 32*i];
                            s0 += wr0[i].x*h4.x + wr0[i].y*h4.y + wr0[i].z*h4.z + wr0[i].w*h4.w;
                            s1 += wr1[i].x*h4.x + wr1[i].y*h4.y + wr1[i].z*h4.z + wr1[i].w*h4.w;
                        }
#pragma unroll
                        for (int o = 16; o; o >>= 1) {
                            s0 += __shfl_xor_sync(0xffffffffu, s0, o);
                            s1 += __shfl_xor_sync(0xffffffffu, s1, o);
                        }
                        if (lane == 0) {
                            int b = chunk*16 + bl;
                            if (half == 0) { sg[lr0][b] = s0; sg[lr1][b] = s1; }
                            else           { sg[lr0][b] += s0; sg[lr1][b] += s1; }
                        }
                    }
                    __syncthreads();
                }
            }
            if (tid < 128) {
                int b = tid >> 2, jj = tid & 3;
                int j = j0 + jj;
                float gi = sg[0  + jj][b] + d_bias1[j];
                float gf = sg[4  + jj][b] + d_bias1[Hz + j];
                float gg = sg[8  + jj][b] + d_bias1[2*Hz + j];
                float go = sg[12 + jj][b] + d_bias1[3*Hz + j];
                int ci = Bz*Hz + b*Hz + j;
                float c = sigf(gf)*d_cstate[ci] + sigf(gi)*tanhf(gg);
                float h = sigf(go)*tanhf(c);
                d_cstate[ci] = c;
                h1n[b*Hz + j] = h;
                d_attq[b*Hz + j] = h + d_cat1[b*Hz + j];
            }
        }
        gbar(nbar);

        // ================= Phase C: attention (no trailing barrier) =============
        // Safe: C reads only d_attq/ctx; A(t+1) writes none of C's inputs, and
        // B(t+1) (which overwrites d_attq) sits behind the bar after A(t+1),
        // which cannot release until every block has finished this phase.
        {
            for (int i = tid; i < Hz; i += NTHR) attq_s[i] = d_attq[cb*Hz + i];
            __syncthreads();

            const float4* A4 = (const float4*)attq_s;
            for (int s = w*16; s < w*16 + 16; ++s) {
                const float4* C4 = (const float4*)(ctx + ((size_t)cb*Sz + s)*Hz);
                float acc = 0.f;
#pragma unroll
                for (int i = 0; i < 4; ++i) {
                    float4 c4 = C4[lane + 32*i];
                    float4 a4 = A4[lane + 32*i];
                    acc += c4.x*a4.x + c4.y*a4.y + c4.z*a4.z + c4.w*a4.w;
                }
#pragma unroll
                for (int o = 16; o; o >>= 1) acc += __shfl_xor_sync(0xffffffffu, acc, o);
                if (lane == 0) sc_s[s] = acc;
            }
            __syncthreads();

            if (w == 0) {
                float m = -1e30f;
                for (int s = lane; s < Sz; s += 32) m = fmaxf(m, sc_s[s]);
#pragma unroll
                for (int o = 16; o; o >>= 1) m = fmaxf(m, __shfl_xor_sync(0xffffffffu, m, o));
                float sm = 0.f;
                for (int s = lane; s < Sz; s += 32) sm += expf(sc_s[s] - m);
#pragma unroll
                for (int o = 16; o; o >>= 1) sm += __shfl_xor_sync(0xffffffffu, sm, o);
                if (lane == 0) s_lse = m + logf(sm);
            }
            __syncthreads();
            float lse = s_lse;

            int h = cq*128 + (tid & 127);
            int sgrp = tid >> 7;
            float acc = 0.f;
            for (int s = sgrp*64; s < sgrp*64 + 64; ++s)
                acc += ctx[((size_t)cb*Sz + s)*Hz + h] * (sc_s[s] - lse);
            s_part[tid] = acc;
            __syncthreads();
            if (tid < 128)
                d_outs[((size_t)cb*Tz + t)*Hz + h] = s_part[tid] + s_part[tid + 128];
            __syncthreads();   // protect sc_s/attq_s reuse next iteration
        }
    }
}

// ---------------- tail: hT, cT ----------------
__global__ void tail_kernel(float* __restrict__ out)
{
    int i = blockIdx.x * blockDim.x + threadIdx.x;
    const size_t base = (size_t)Bz*Tz*Vz;
    if (i < Bz*Hz)                 out[base + i] = d_h0buf[i];       // T even -> buf 0
    else if (i < 2*Bz*Hz)          out[base + i] = d_h1buf[i - Bz*Hz];
    else if (i < 4*Bz*Hz)          out[base + i] = d_cstate[i - 2*Bz*Hz];
}

// ---------------- launch ----------------
extern "C" void kernel_launch(void* const* d_in, const int* in_sizes, int n_in,
                              void* d_out, int out_size)
{
    const float* context = (const float*)d_in[0];
    const int*   dec     = (const int*)d_in[1];
    const float* h0      = (const float*)d_in[2];
    const float* c0      = (const float*)d_in[3];
    const float* emb     = (const float*)d_in[4];
    const float* Wih     = (const float*)d_in[5];
    const float* Whh     = (const float*)d_in[6];
    const float* bih     = (const float*)d_in[7];
    const float* bhh     = (const float*)d_in[8];
    const float* Wc      = (const float*)d_in[9];
    const float* bc      = (const float*)d_in[10];
    float* out = (float*)d_out;

    float *p_x, *p_g0ih, *p_outs, *p_b0;
    cudaGetSymbolAddress((void**)&p_x,    d_x);
    cudaGetSymbolAddress((void**)&p_g0ih, d_g0ih);
    cudaGetSymbolAddress((void**)&p_outs, d_outs);
    cudaGetSymbolAddress((void**)&p_b0,   d_bias0);

    reset_kernel<<<1, 1>>>();
    prep_kernel<<<(Gz*2*Hz + 255)/256, 256>>>(Wih, Whh, bih, bhh, h0, c0);
    embed_kernel<<<(Tz*Bz*Hz + 255)/256, 256>>>(dec, emb);

    // layer0 ih gates for ALL timesteps
    {
        dim3 grid(Gz/64, (Tz*Bz)/128);
        gemm_abt<128,64,16,8,4><<<grid, 256>>>(p_x, Wih, p_b0, p_g0ih, Tz*Bz, Gz, Hz);
    }

    // persistent scan
    scan_kernel<<<NBLK, NTHR>>>(context, Whh);

    // logits: [B*T, V] = outs @ Wc^T + bc
    {
        dim3 grid(Vz/64, (Bz*Tz)/128);
        gemm_abt<128,64,16,8,4><<<grid, 256>>>(p_outs, Wc, bc, out, Bz*Tz, Vz, Hz);
    }

    if ((long long)out_size >= (long long)Bz*Tz*Vz + 4LL*Bz*Hz) {
        tail_kernel<<<(4*Bz*Hz + 255)/256, 256>>>(out);
    }
}